// round 1
// baseline (speedup 1.0000x reference)
#include <cuda_runtime.h>
#include <cuda_bf16.h>

// ---------------------------------------------------------------------------
// SharedGroupGRU: N=512, NUM_HIDDEN=32 -> B=16384 rows, IN=HID=128, KEY=64,
// RULES=16. Forward-pass simplifications:
//   att == y_hard (one-hot of argmax(logits+gumbel)), softmax/tau monotone.
//   logits[b,r] = q[b] . hnext[b,r],  q = H @ (w_read @ W_write).
// Heavy work: grouped GRU GEMMs, done in FP32 with packed fma.rn.f32x2.
// ---------------------------------------------------------------------------

#define BTOT   16384      // N * NUM_HIDDEN
#define KDIM   128        // IN == HID
#define RULES  16
#define TM     64         // b-rows per CTA
#define TN     32         // h-cols per CTA
#define KC     32         // k-chunk

typedef unsigned long long u64;

// scratch (static device arrays; runtime allocation is forbidden)
__device__ float g_M[KDIM * KDIM];                    // w_read @ W_write   [128,128]
__device__ float g_q[BTOT * KDIM];                    // H @ M              [B,128]
__device__ float g_hnext[(size_t)BTOT * RULES * KDIM];// GRU outputs        [B,R,128]

// ---- packed f32x2 helpers --------------------------------------------------
__device__ __forceinline__ u64 pack2(float x, float y) {
    u64 r;
    asm("mov.b64 %0, {%1, %2};" : "=l"(r) : "f"(x), "f"(y));
    return r;
}
__device__ __forceinline__ void unpack2(u64 v, float& x, float& y) {
    asm("mov.b64 {%0, %1}, %2;" : "=f"(x), "=f"(y) : "l"(v));
}
__device__ __forceinline__ void ffma2(u64& d, u64 a, u64 b) {
    asm("fma.rn.f32x2 %0, %1, %2, %0;" : "+l"(d) : "l"(a), "l"(b));
}

__device__ __forceinline__ float sigf(float x) {
    return __fdividef(1.0f, 1.0f + __expf(-x));
}
__device__ __forceinline__ float tanhf_fast(float x) {
    // 1 - 2/(e^{2x}+1); correct limits at +/-inf with __expf/__fdividef
    float e = __expf(2.0f * x);
    return 1.0f - __fdividef(2.0f, e + 1.0f);
}

// ---------------------------------------------------------------------------
// Kernel M: g_M[hp][h] = sum_k w_read[hp*64+k] * W_write[k*128+h]
// ---------------------------------------------------------------------------
__global__ void kM(const float* __restrict__ wread, const float* __restrict__ wwrite) {
    for (int o = threadIdx.x; o < KDIM * KDIM; o += blockDim.x) {
        int hp = o >> 7, h = o & 127;
        float s = 0.0f;
        #pragma unroll 8
        for (int k = 0; k < 64; ++k)
            s = fmaf(wread[hp * 64 + k], wwrite[k * 128 + h], s);
        g_M[o] = s;
    }
}

// ---------------------------------------------------------------------------
// Kernel Q: g_q = H @ g_M.   16 b-rows per block, 256 threads.
// ---------------------------------------------------------------------------
__global__ void kQ(const float* __restrict__ Hin) {
    __shared__ float Hs[16][KDIM];
    int b0 = blockIdx.x * 16;
    for (int i = threadIdx.x; i < 16 * KDIM; i += blockDim.x)
        Hs[i >> 7][i & 127] = Hin[b0 * KDIM + i];
    __syncthreads();

    int h  = threadIdx.x & 127;
    int rr = threadIdx.x >> 7;   // 0..1
    float acc[8];
    #pragma unroll
    for (int j = 0; j < 8; ++j) acc[j] = 0.0f;

    for (int k = 0; k < KDIM; ++k) {
        float m = g_M[k * KDIM + h];           // coalesced; broadcast-friendly
        #pragma unroll
        for (int j = 0; j < 8; ++j)
            acc[j] = fmaf(Hs[rr + 2 * j][k], m, acc[j]);
    }
    #pragma unroll
    for (int j = 0; j < 8; ++j)
        g_q[(size_t)(b0 + rr + 2 * j) * KDIM + h] = acc[j];
}

// ---------------------------------------------------------------------------
// Kernel GRU: fused grouped GEMM + gates.
// grid = (B/TM, KDIM/TN, RULES); block = 256 = 16 tx (col pairs) x 16 ty (4-row)
// Per thread: 4 rows x 2 cols x 6 gate accumulators as 24 packed f32x2.
// ---------------------------------------------------------------------------
__global__ void __launch_bounds__(256, 2)
kGRU(const float* __restrict__ X, const float* __restrict__ Hin,
     const float* __restrict__ Wih, const float* __restrict__ Whh,
     const float* __restrict__ bih, const float* __restrict__ bhh) {
    __shared__ float Xs[TM][36];          // [row][kk] (pad 36: float4-store + bcast reads)
    __shared__ float Hs[TM][36];
    __shared__ float Wi[3][KC][34];       // [gate][kk][col] (pad 34: 2-way store conflict)
    __shared__ float Wh[3][KC][34];

    const int b0 = blockIdx.x * TM;
    const int h0 = blockIdx.y * TN;
    const int r  = blockIdx.z;
    const int tid = threadIdx.x;
    const int tx = tid & 15;              // col-pair index
    const int ty = tid >> 4;              // 4-row group
    const int c0 = 2 * tx;

    const float* Wr = Wih + (size_t)r * 384 * KDIM;
    const float* Wh_g = Whh + (size_t)r * 384 * KDIM;

    u64 a_ir[4], a_iz[4], a_in[4], a_hr[4], a_hz[4], a_hn[4];
    #pragma unroll
    for (int j = 0; j < 4; ++j)
        a_ir[j] = a_iz[j] = a_in[j] = a_hr[j] = a_hz[j] = a_hn[j] = 0ull;

    float hprev[4][2];

    for (int kc = 0; kc < KDIM / KC; ++kc) {
        const int k0 = kc * KC;
        if (kc) __syncthreads();

        // load X/H tiles transposed-access-friendly (row-major, float4)
        for (int i = tid; i < TM * KC / 4; i += 256) {
            int row = i >> 3, kk4 = (i & 7) << 2;
            float4 vx = *reinterpret_cast<const float4*>(X  + (size_t)(b0 + row) * KDIM + k0 + kk4);
            float4 vh = *reinterpret_cast<const float4*>(Hin + (size_t)(b0 + row) * KDIM + k0 + kk4);
            *reinterpret_cast<float4*>(&Xs[row][kk4]) = vx;
            *reinterpret_cast<float4*>(&Hs[row][kk4]) = vh;
        }
        // load weight slices: [gate][kk][col], global is k-contiguous (coalesced)
        for (int i = tid; i < 3 * KC * TN; i += 256) {
            int kk = i & 31, c = (i >> 5) & 31, g = i >> 10;
            Wi[g][kk][c] = Wr  [(size_t)(g * 128 + h0 + c) * KDIM + k0 + kk];
            Wh[g][kk][c] = Wh_g[(size_t)(g * 128 + h0 + c) * KDIM + k0 + kk];
        }
        __syncthreads();

        #pragma unroll
        for (int kk = 0; kk < KC; ++kk) {
            u64 wir = *reinterpret_cast<const u64*>(&Wi[0][kk][c0]);
            u64 wiz = *reinterpret_cast<const u64*>(&Wi[1][kk][c0]);
            u64 win = *reinterpret_cast<const u64*>(&Wi[2][kk][c0]);
            u64 whr = *reinterpret_cast<const u64*>(&Wh[0][kk][c0]);
            u64 whz = *reinterpret_cast<const u64*>(&Wh[1][kk][c0]);
            u64 whn = *reinterpret_cast<const u64*>(&Wh[2][kk][c0]);
            #pragma unroll
            for (int j = 0; j < 4; ++j) {
                float ax = Xs[4 * ty + j][kk];
                u64 ax2 = pack2(ax, ax);
                ffma2(a_ir[j], ax2, wir);
                ffma2(a_iz[j], ax2, wiz);
                ffma2(a_in[j], ax2, win);
                float ah = Hs[4 * ty + j][kk];
                u64 ah2 = pack2(ah, ah);
                ffma2(a_hr[j], ah2, whr);
                ffma2(a_hz[j], ah2, whz);
                ffma2(a_hn[j], ah2, whn);
            }
        }
        // grab previous-h values for our output columns while resident
        if (kc == (int)blockIdx.y) {
            #pragma unroll
            for (int j = 0; j < 4; ++j) {
                hprev[j][0] = Hs[4 * ty + j][c0];
                hprev[j][1] = Hs[4 * ty + j][c0 + 1];
            }
        }
    }

    // biases (broadcast loads, L2-resident)
    float bir[2], biz[2], bin_[2], bhr[2], bhz[2], bhn[2];
    #pragma unroll
    for (int cc = 0; cc < 2; ++cc) {
        int c = h0 + c0 + cc;
        bir[cc]  = bih[r * 384 + c];
        biz[cc]  = bih[r * 384 + 128 + c];
        bin_[cc] = bih[r * 384 + 256 + c];
        bhr[cc]  = bhh[r * 384 + c];
        bhz[cc]  = bhh[r * 384 + 128 + c];
        bhn[cc]  = bhh[r * 384 + 256 + c];
    }

    #pragma unroll
    for (int j = 0; j < 4; ++j) {
        float ir0, ir1, iz0, iz1, in0, in1, hr0, hr1, hz0, hz1, hn0, hn1;
        unpack2(a_ir[j], ir0, ir1);
        unpack2(a_iz[j], iz0, iz1);
        unpack2(a_in[j], in0, in1);
        unpack2(a_hr[j], hr0, hr1);
        unpack2(a_hz[j], hz0, hz1);
        unpack2(a_hn[j], hn0, hn1);

        float out01[2];
        #pragma unroll
        for (int cc = 0; cc < 2; ++cc) {
            float ir = (cc ? ir1 : ir0) + bir[cc];
            float iz = (cc ? iz1 : iz0) + biz[cc];
            float in_ = (cc ? in1 : in0) + bin_[cc];
            float hr = (cc ? hr1 : hr0) + bhr[cc];
            float hz = (cc ? hz1 : hz0) + bhz[cc];
            float hn = (cc ? hn1 : hn0) + bhn[cc];
            float rg = sigf(ir + hr);
            float zg = sigf(iz + hz);
            float nn = tanhf_fast(fmaf(rg, hn, in_));
            out01[cc] = fmaf(zg, hprev[j][cc] - nn, nn);   // (1-z)*n + z*h
        }
        size_t row = b0 + 4 * ty + j;
        float2 v; v.x = out01[0]; v.y = out01[1];
        *reinterpret_cast<float2*>(&g_hnext[(row * RULES + r) * KDIM + h0 + c0]) = v;
    }
}

// ---------------------------------------------------------------------------
// Kernel Select: per b — logits[r] = q[b].hnext[b,r]; argmax(logits+gumbel);
// h_out = hnext[b,rbest]; attn = one-hot. One warp per b.
// ---------------------------------------------------------------------------
__global__ void kSelect(const float* __restrict__ gumbel,
                        float* __restrict__ out_h, float* __restrict__ out_attn) {
    int gwarp = (blockIdx.x * blockDim.x + threadIdx.x) >> 5;
    int lane = threadIdx.x & 31;
    if (gwarp >= BTOT) return;
    const int b = gwarp;

    float4 q4 = *reinterpret_cast<const float4*>(g_q + (size_t)b * KDIM + lane * 4);
    const float* hb = g_hnext + (size_t)b * RULES * KDIM;

    float myLogit = -__int_as_float(0x7f800000);  // -inf
    #pragma unroll
    for (int r = 0; r < RULES; ++r) {
        float4 v = *reinterpret_cast<const float4*>(hb + r * KDIM + lane * 4);
        float p = q4.x * v.x + q4.y * v.y + q4.z * v.z + q4.w * v.w;
        #pragma unroll
        for (int off = 16; off; off >>= 1)
            p += __shfl_xor_sync(0xffffffffu, p, off);
        if (lane == r) myLogit = p + gumbel[b * RULES + r];
    }

    float bv = myLogit; int bi = lane;
    #pragma unroll
    for (int off = 16; off; off >>= 1) {
        float ov = __shfl_xor_sync(0xffffffffu, bv, off);
        int   oi = __shfl_xor_sync(0xffffffffu, bi, off);
        if (ov > bv || (ov == bv && oi < bi)) { bv = ov; bi = oi; }
    }
    int rbest = bi;

    float4 hv = *reinterpret_cast<const float4*>(hb + rbest * KDIM + lane * 4);
    *reinterpret_cast<float4*>(out_h + (size_t)b * KDIM + lane * 4) = hv;
    if (out_attn && lane < RULES)
        out_attn[b * RULES + lane] = (lane == rbest) ? 1.0f : 0.0f;
}

// ---------------------------------------------------------------------------
extern "C" void kernel_launch(void* const* d_in, const int* in_sizes, int n_in,
                              void* d_out, int out_size) {
    const float* X      = (const float*)d_in[0];  // input   [B,128]
    const float* H      = (const float*)d_in[1];  // h       [B,128]
    const float* Wih    = (const float*)d_in[2];  // [16,384,128]
    const float* Whh    = (const float*)d_in[3];  // [16,384,128]
    const float* bih    = (const float*)d_in[4];  // [16,384]
    const float* bhh    = (const float*)d_in[5];  // [16,384]
    const float* wread  = (const float*)d_in[6];  // [1,128,64]
    const float* wwrite = (const float*)d_in[7];  // [64,128]
    const float* gum    = (const float*)d_in[8];  // [B,1,16]
    float* out = (float*)d_out;

    kM<<<1, 256>>>(wread, wwrite);
    kQ<<<BTOT / 16, 256>>>(H);

    dim3 grid(BTOT / TM, KDIM / TN, RULES);
    kGRU<<<grid, 256>>>(X, H, Wih, Whh, bih, bhh);

    const int HO = BTOT * KDIM;               // 2,097,152 h_out elements
    float* attn = (out_size >= HO + BTOT * RULES) ? out + HO : nullptr;
    kSelect<<<BTOT / 8, 256>>>(gum, out, attn);
}

// round 4
// speedup vs baseline: 1.6342x; 1.6342x over previous
#include <cuda_runtime.h>
#include <cuda_bf16.h>
#include <cstdint>

// ---------------------------------------------------------------------------
// SharedGroupGRU: B=16384 rows, IN=HID=128, KEY=64, RULES=16.
//   att == y_hard (argmax of logits+gumbel); logits[b,r] = q[b].hnext[b,r],
//   q = H @ (w_read @ W_write).
// Grouped GRU GEMMs via mma.sync.m16n8k16 bf16 (harness targets compute_100,
// so tcgen05 is unavailable). 2-term bf16 split (hh + hl + lh), fp32 register
// accumulators, cp.async double-buffering.
// CTA = 64 b-rows x 1 rule; r/z gate pre-acts summed across both GEMM sides
// in-register; i_n, h_n kept separate for tanh(i_n + r*h_n).
// (Re-run of round-3 kernel: previous bench died to a broker/container flake
// before compile; kernel re-audited — fragments, swizzle, pipeline, bounds OK.)
// ---------------------------------------------------------------------------

#define BTOT   16384
#define KDIM   128
#define RULES  16
#define TM     64

typedef unsigned long long u64;

// -------------------- device scratch (static; no runtime alloc) ------------
__device__ float g_M[KDIM * KDIM];
__device__ float g_q[BTOT * KDIM];
__device__ float g_hnext[(size_t)BTOT * RULES * KDIM];

__device__ __nv_bfloat16 g_Xh[BTOT * KDIM], g_Xl[BTOT * KDIM];
__device__ __nv_bfloat16 g_Hh[BTOT * KDIM], g_Hl[BTOT * KDIM];
__device__ __nv_bfloat16 g_Wih_h[RULES * 384 * KDIM], g_Wih_l[RULES * 384 * KDIM];
__device__ __nv_bfloat16 g_Whh_h[RULES * 384 * KDIM], g_Whh_l[RULES * 384 * KDIM];

// -------------------- helpers ----------------------------------------------
__device__ __forceinline__ uint32_t smem_u32(const void* p) {
    uint32_t a;
    asm("{ .reg .u64 t; cvta.to.shared.u64 t, %1; cvt.u32.u64 %0, t; }" : "=r"(a) : "l"(p));
    return a;
}
__device__ __forceinline__ void cpasync16(uint32_t dst, const void* src) {
    asm volatile("cp.async.cg.shared.global [%0], [%1], 16;" :: "r"(dst), "l"(src));
}
__device__ __forceinline__ void ldsm4(uint32_t* r, uint32_t a) {
    asm volatile("ldmatrix.sync.aligned.m8n8.x4.shared.b16 {%0,%1,%2,%3}, [%4];"
                 : "=r"(r[0]), "=r"(r[1]), "=r"(r[2]), "=r"(r[3]) : "r"(a));
}
__device__ __forceinline__ void ldsm2(uint32_t* r, uint32_t a) {
    asm volatile("ldmatrix.sync.aligned.m8n8.x2.shared.b16 {%0,%1}, [%2];"
                 : "=r"(r[0]), "=r"(r[1]) : "r"(a));
}
__device__ __forceinline__ void mma16816(float* d, const uint32_t* a, const uint32_t* b) {
    asm volatile("mma.sync.aligned.m16n8k16.row.col.f32.bf16.bf16.f32 "
                 "{%0,%1,%2,%3}, {%4,%5,%6,%7}, {%8,%9}, {%0,%1,%2,%3};"
                 : "+f"(d[0]), "+f"(d[1]), "+f"(d[2]), "+f"(d[3])
                 : "r"(a[0]), "r"(a[1]), "r"(a[2]), "r"(a[3]), "r"(b[0]), "r"(b[1]));
}
__device__ __forceinline__ float sigf(float x) {
    return __fdividef(1.0f, 1.0f + __expf(-x));
}
__device__ __forceinline__ float tanhf_fast(float x) {
    float e = __expf(2.0f * x);
    return 1.0f - __fdividef(2.0f, e + 1.0f);
}

// -------------------- smem geometry ----------------------------------------
// stage: A tiles (Xh,Xl,Hh,Hl : 64 rows x 32 k bf16 = 4KB each) = 16KB
//        B tiles (12 arrays: [side][gate][lvl], 128 rows x 32 k = 8KB) = 96KB
#define A_SZ        4096
#define B_SZ        8192
#define B_OFF       16384
#define STAGE_BYTES 114688                 // 112KB
#define SMEM_TOTAL  (2 * STAGE_BYTES)      // 224KB

// ---------------------------------------------------------------------------
// kConvAll: fp32 -> (bf16 hi, bf16 lo) splits for X, H, Wih, Whh
// ---------------------------------------------------------------------------
__global__ void kConvAll(const float* __restrict__ X, const float* __restrict__ H,
                         const float* __restrict__ Wih, const float* __restrict__ Whh) {
    const int NA = BTOT * KDIM;
    const int NW = RULES * 384 * KDIM;
    int i = blockIdx.x * blockDim.x + threadIdx.x;
    if (i < NA) {
        float v = X[i];
        __nv_bfloat16 h = __float2bfloat16(v);
        g_Xh[i] = h; g_Xl[i] = __float2bfloat16(v - __bfloat162float(h));
        v = H[i];
        h = __float2bfloat16(v);
        g_Hh[i] = h; g_Hl[i] = __float2bfloat16(v - __bfloat162float(h));
    }
    if (i < NW) {
        float v = Wih[i];
        __nv_bfloat16 h = __float2bfloat16(v);
        g_Wih_h[i] = h; g_Wih_l[i] = __float2bfloat16(v - __bfloat162float(h));
        v = Whh[i];
        h = __float2bfloat16(v);
        g_Whh_h[i] = h; g_Whh_l[i] = __float2bfloat16(v - __bfloat162float(h));
    }
}

// ---------------------------------------------------------------------------
// kM: g_M = w_read @ W_write  [128x128]
// ---------------------------------------------------------------------------
__global__ void kM(const float* __restrict__ wread, const float* __restrict__ wwrite) {
    for (int o = threadIdx.x; o < KDIM * KDIM; o += blockDim.x) {
        int hp = o >> 7, h = o & 127;
        float s = 0.0f;
        #pragma unroll 8
        for (int k = 0; k < 64; ++k)
            s = fmaf(wread[hp * 64 + k], wwrite[k * 128 + h], s);
        g_M[o] = s;
    }
}

// ---------------------------------------------------------------------------
// kQ: g_q = H @ g_M (fp32; feeds argmax path)
// ---------------------------------------------------------------------------
__global__ void kQ(const float* __restrict__ Hin) {
    __shared__ float Hs[16][KDIM];
    int b0 = blockIdx.x * 16;
    for (int i = threadIdx.x; i < 16 * KDIM; i += blockDim.x)
        Hs[i >> 7][i & 127] = Hin[b0 * KDIM + i];
    __syncthreads();

    int h  = threadIdx.x & 127;
    int rr = threadIdx.x >> 7;
    float acc[8];
    #pragma unroll
    for (int j = 0; j < 8; ++j) acc[j] = 0.0f;
    for (int k = 0; k < KDIM; ++k) {
        float m = g_M[k * KDIM + h];
        #pragma unroll
        for (int j = 0; j < 8; ++j)
            acc[j] = fmaf(Hs[rr + 2 * j][k], m, acc[j]);
    }
    #pragma unroll
    for (int j = 0; j < 8; ++j)
        g_q[(size_t)(b0 + rr + 2 * j) * KDIM + h] = acc[j];
}

// ---------------------------------------------------------------------------
// kGRU: grid (256, 16), block 512.
// Warp w: rg = w&1 (32-row group), u = w>>1:
//   heavy plane = r_sum (u<4) / z_sum (u>=4): 6 products (X&H sides)
//   light plane = i_n (u<4, X side) / h_n (u>=4, H side): 3 products
//   cols (u&3)*32 .. +32 within the 128 h-cols.
// ---------------------------------------------------------------------------
__device__ __forceinline__ void load_stage(uint32_t sb, int b0, int rule,
                                           int tid, int chunk, int buf) {
    const int k0 = chunk * 32;
    const uint32_t stb = sb + buf * STAGE_BYTES;
    // A tiles: 1024 x 16B ops -> 2 per thread
    {
        int row = (tid >> 2) & 63, c = tid & 3;
        uint32_t sw = (uint32_t)((c ^ ((row >> 1) & 3)) << 4);
        size_t srcoff = (size_t)(b0 + row) * KDIM + k0 + c * 8;
        const __nv_bfloat16* pX = (tid & 256) ? g_Xl : g_Xh;
        const __nv_bfloat16* pH = (tid & 256) ? g_Hl : g_Hh;
        uint32_t arr0 = (tid >> 8) & 1;
        cpasync16(stb + arr0 * A_SZ + row * 64 + sw, pX + srcoff);
        cpasync16(stb + (2 + arr0) * A_SZ + row * 64 + sw, pH + srcoff);
    }
    // B tiles: 12 arrays x 512 ops -> 12 per thread
    {
        int row = tid >> 2, c = tid & 3;
        uint32_t sw = (uint32_t)((c ^ ((row >> 1) & 3)) << 4);
        uint32_t dbase = stb + B_OFF + row * 64 + sw;
        #pragma unroll
        for (int s = 0; s < 2; ++s) {
            #pragma unroll
            for (int g = 0; g < 3; ++g) {
                size_t srcoff = ((size_t)rule * 384 + g * 128 + row) * KDIM + k0 + c * 8;
                #pragma unroll
                for (int v = 0; v < 2; ++v) {
                    const __nv_bfloat16* base =
                        s ? (v ? g_Whh_l : g_Whh_h) : (v ? g_Wih_l : g_Wih_h);
                    int a = (s * 3 + g) * 2 + v;
                    cpasync16(dbase + a * B_SZ, base + srcoff);
                }
            }
        }
    }
    asm volatile("cp.async.commit_group;" ::: "memory");
}

__global__ void __launch_bounds__(512, 1)
kGRU(const float* __restrict__ Hin,
     const float* __restrict__ bih, const float* __restrict__ bhh) {
    extern __shared__ char smem[];
    const uint32_t sb = smem_u32(smem);
    const int tid  = threadIdx.x;
    const int w    = tid >> 5, lane = tid & 31;
    const int b0   = blockIdx.x * TM;
    const int rule = blockIdx.y;

    const int rg = w & 1;
    const int u  = w >> 1;
    const int gh = u >> 2;                  // heavy gate: 0=r, 1=z
    const int lightSide = (u < 4) ? 0 : 1;  // i_n on X-side, h_n on H-side
    const int n0 = (u & 3) * 32;

    // lane-invariant ldmatrix address components
    const int rowa = rg * 32 + (lane & 15);       // + mt*16
    const uint32_t aoff = (uint32_t)rowa * 64;
    const int swa = ((lane & 15) >> 1) & 3;
    const int hiA = lane >> 4;
    const int rowb = n0 + (lane & 7);
    const uint32_t boff = (uint32_t)rowb * 64;
    const int swb = ((lane & 7) >> 1) & 3;
    const int hiB = (lane >> 3) & 1;

    float accH[2][4][4], accL[2][4][4];
    #pragma unroll
    for (int mt = 0; mt < 2; ++mt)
        #pragma unroll
        for (int nt = 0; nt < 4; ++nt)
            #pragma unroll
            for (int j = 0; j < 4; ++j) { accH[mt][nt][j] = 0.0f; accL[mt][nt][j] = 0.0f; }

    load_stage(sb, b0, rule, tid, 0, 0);
    load_stage(sb, b0, rule, tid, 1, 1);

    #pragma unroll
    for (int c = 0; c < 4; ++c) {
        if (c < 3) asm volatile("cp.async.wait_group 1;" ::: "memory");
        else       asm volatile("cp.async.wait_group 0;" ::: "memory");
        __syncthreads();

        const uint32_t stb = sb + (c & 1) * STAGE_BYTES;
        #pragma unroll
        for (int ks = 0; ks < 2; ++ks) {
            const uint32_t kxa = (uint32_t)(((ks * 2 + hiA) ^ swa) << 4);
            const uint32_t kxb = (uint32_t)(((ks * 2 + hiB) ^ swb) << 4);
            #pragma unroll
            for (int s = 0; s < 2; ++s) {
                uint32_t ah[2][4], al[2][4];
                const uint32_t baseA = stb + (2 * s) * A_SZ;
                ldsm4(ah[0], baseA + aoff + kxa);
                ldsm4(ah[1], baseA + aoff + 1024 + kxa);          // +16 rows*64B
                ldsm4(al[0], baseA + A_SZ + aoff + kxa);
                ldsm4(al[1], baseA + A_SZ + aoff + 1024 + kxa);

                // heavy plane (r or z): accumulate both sides into accH
                const uint32_t bbH = stb + B_OFF + (uint32_t)((s * 3 + gh) * 2) * B_SZ;
                #pragma unroll
                for (int nt = 0; nt < 4; ++nt) {
                    uint32_t bh[2], bl[2];
                    ldsm2(bh, bbH + boff + nt * 512 + kxb);
                    ldsm2(bl, bbH + B_SZ + boff + nt * 512 + kxb);
                    #pragma unroll
                    for (int mt = 0; mt < 2; ++mt) {
                        mma16816(accH[mt][nt], ah[mt], bh);
                        mma16816(accH[mt][nt], ah[mt], bl);
                        mma16816(accH[mt][nt], al[mt], bh);
                    }
                }
                // light plane (i_n or h_n): single side
                if (s == lightSide) {
                    const uint32_t bbL = stb + B_OFF + (uint32_t)((s * 3 + 2) * 2) * B_SZ;
                    #pragma unroll
                    for (int nt = 0; nt < 4; ++nt) {
                        uint32_t bh[2], bl[2];
                        ldsm2(bh, bbL + boff + nt * 512 + kxb);
                        ldsm2(bl, bbL + B_SZ + boff + nt * 512 + kxb);
                        #pragma unroll
                        for (int mt = 0; mt < 2; ++mt) {
                            mma16816(accL[mt][nt], ah[mt], bh);
                            mma16816(accL[mt][nt], ah[mt], bl);
                            mma16816(accL[mt][nt], al[mt], bh);
                        }
                    }
                }
            }
        }
        if (c < 2) {
            __syncthreads();                      // buffer free before refill
            load_stage(sb, b0, rule, tid, c + 2, c & 1);
        }
    }
    __syncthreads();                              // all MMA reads done

    // ---- stage accums to smem: 4 planes x [64 rows x 128 cols] fp32 = 128KB
    float* stg = (float*)smem;
    const int PL = (u < 4) ? 2 : 3;
    #pragma unroll
    for (int mt = 0; mt < 2; ++mt) {
        #pragma unroll
        for (int nt = 0; nt < 4; ++nt) {
            int prow = rg * 32 + mt * 16 + (lane >> 2);
            int pcol = n0 + nt * 8 + (lane & 3) * 2;
            float* pH = stg + gh * 8192 + prow * 128 + pcol;
            pH[0] = accH[mt][nt][0]; pH[1] = accH[mt][nt][1];
            pH[8 * 128] = accH[mt][nt][2]; pH[8 * 128 + 1] = accH[mt][nt][3];
            float* pL = stg + PL * 8192 + prow * 128 + pcol;
            pL[0] = accL[mt][nt][0]; pL[1] = accL[mt][nt][1];
            pL[8 * 128] = accL[mt][nt][2]; pL[8 * 128 + 1] = accL[mt][nt][3];
        }
    }
    __syncthreads();

    // ---- gate math + store: thread -> (row, 16 cols)
    {
        const int row = tid >> 3;
        const int c0  = (tid & 7) * 16;
        const float* bi = bih + rule * 384;
        const float* bh = bhh + rule * 384;
        const float* hprow = Hin + (size_t)(b0 + row) * KDIM;
        float* dst = g_hnext + ((size_t)(b0 + row) * RULES + rule) * KDIM + c0;
        float out[16];
        #pragma unroll
        for (int q = 0; q < 16; ++q) {
            int cc = c0 + q;
            float ar  = stg[          row * 128 + cc] + bi[cc] + bh[cc];
            float az  = stg[ 8192 +   row * 128 + cc] + bi[128 + cc] + bh[128 + cc];
            float xin = stg[16384 +   row * 128 + cc] + bi[256 + cc];
            float xhn = stg[24576 +   row * 128 + cc] + bh[256 + cc];
            float rgate = sigf(ar);
            float zgate = sigf(az);
            float nn = tanhf_fast(fmaf(rgate, xhn, xin));
            out[q] = fmaf(zgate, hprow[cc] - nn, nn);
        }
        #pragma unroll
        for (int q4 = 0; q4 < 4; ++q4)
            *reinterpret_cast<float4*>(dst + q4 * 4) =
                *reinterpret_cast<const float4*>(&out[q4 * 4]);
    }
}

// ---------------------------------------------------------------------------
// kSelect: logits+gumbel argmax, gather h_out, one-hot attn. One warp per b.
// ---------------------------------------------------------------------------
__global__ void kSelect(const float* __restrict__ gumbel,
                        float* __restrict__ out_h, float* __restrict__ out_attn) {
    int gwarp = (blockIdx.x * blockDim.x + threadIdx.x) >> 5;
    int lane = threadIdx.x & 31;
    if (gwarp >= BTOT) return;
    const int b = gwarp;

    float4 q4 = *reinterpret_cast<const float4*>(g_q + (size_t)b * KDIM + lane * 4);
    const float* hb = g_hnext + (size_t)b * RULES * KDIM;

    float myLogit = -__int_as_float(0x7f800000);
    #pragma unroll
    for (int r = 0; r < RULES; ++r) {
        float4 v = *reinterpret_cast<const float4*>(hb + r * KDIM + lane * 4);
        float p = q4.x * v.x + q4.y * v.y + q4.z * v.z + q4.w * v.w;
        #pragma unroll
        for (int off = 16; off; off >>= 1)
            p += __shfl_xor_sync(0xffffffffu, p, off);
        if (lane == r) myLogit = p + gumbel[b * RULES + r];
    }

    float bv = myLogit; int bi = lane;
    #pragma unroll
    for (int off = 16; off; off >>= 1) {
        float ov = __shfl_xor_sync(0xffffffffu, bv, off);
        int   oi = __shfl_xor_sync(0xffffffffu, bi, off);
        if (ov > bv || (ov == bv && oi < bi)) { bv = ov; bi = oi; }
    }
    int rbest = bi;

    float4 hv = *reinterpret_cast<const float4*>(hb + rbest * KDIM + lane * 4);
    *reinterpret_cast<float4*>(out_h + (size_t)b * KDIM + lane * 4) = hv;
    if (out_attn && lane < RULES)
        out_attn[b * RULES + lane] = (lane == rbest) ? 1.0f : 0.0f;
}

// ---------------------------------------------------------------------------
extern "C" void kernel_launch(void* const* d_in, const int* in_sizes, int n_in,
                              void* d_out, int out_size) {
    const float* X      = (const float*)d_in[0];
    const float* H      = (const float*)d_in[1];
    const float* Wih    = (const float*)d_in[2];
    const float* Whh    = (const float*)d_in[3];
    const float* bih    = (const float*)d_in[4];
    const float* bhh    = (const float*)d_in[5];
    const float* wread  = (const float*)d_in[6];
    const float* wwrite = (const float*)d_in[7];
    const float* gum    = (const float*)d_in[8];
    float* out = (float*)d_out;

    // host-side attribute set; idempotent, not a stream op (capture-safe)
    cudaFuncSetAttribute(kGRU, cudaFuncAttributeMaxDynamicSharedMemorySize, SMEM_TOTAL);

    const int NA = BTOT * KDIM;
    kConvAll<<<(NA + 255) / 256, 256>>>(X, H, Wih, Whh);
    kM<<<1, 256>>>(wread, wwrite);
    kQ<<<BTOT / 16, 256>>>(H);

    dim3 grid(BTOT / TM, RULES);
    kGRU<<<grid, 512, SMEM_TOTAL>>>(H, bih, bhh);

    const int HO = BTOT * KDIM;
    float* attn = (out_size >= HO + BTOT * RULES) ? out + HO : nullptr;
    kSelect<<<BTOT / 8, 256>>>(gum, out, attn);
}

// round 6
// speedup vs baseline: 1.6740x; 1.0244x over previous
#include <cuda_runtime.h>
#include <cuda_bf16.h>
#include <cstdint>

// ---------------------------------------------------------------------------
// SharedGroupGRU: B=16384 rows, IN=HID=128, KEY=64, RULES=16.
//   att == y_hard (argmax of logits+gumbel); logits[b,r] = q[b].hnext[b,r],
//   q = H @ (w_read @ W_write).
// Same validated bf16-split HMMA math (hh + hl + lh, fp32 accum),
// restructured for occupancy: 1024 threads / 32 warps per CTA (<=64 regs),
// ldsm4-only fragment loads, logits computed in kGRU epilogue, gather-only
// select kernel.
// (Re-run: round-5 bench died to the recurring broker/container flake before
// compile; kernel re-audited — fragments, swizzle, coverage, ordering OK.)
// ---------------------------------------------------------------------------

#define BTOT   16384
#define KDIM   128
#define RULES  16
#define TM     64
#define NA     (BTOT * KDIM)          // 2,097,152
#define NW     (RULES * 384 * KDIM)   // 786,432

typedef unsigned long long u64;

// -------------------- device scratch (static; no runtime alloc) ------------
__device__ float g_M[KDIM * KDIM];
__device__ float g_q[BTOT * KDIM];
__device__ float g_logits[BTOT * RULES];
__device__ float g_hnext[(size_t)BTOT * RULES * KDIM];

// A slabs: arr 0=Xh 1=Xl 2=Hh 3=Hl, each [BTOT][128]
__device__ __nv_bfloat16 g_Asp[4 * NA];
// W slabs: arr = (s*3+g)*2 + lvl (s:0=ih,1=hh; g:r,z,n; lvl:0=hi,1=lo),
// each [RULES][128][128]
__device__ __nv_bfloat16 g_Wsp[12 * RULES * 128 * KDIM];

// -------------------- helpers ----------------------------------------------
__device__ __forceinline__ uint32_t smem_u32(const void* p) {
    uint32_t a;
    asm("{ .reg .u64 t; cvta.to.shared.u64 t, %1; cvt.u32.u64 %0, t; }" : "=r"(a) : "l"(p));
    return a;
}
__device__ __forceinline__ void cpasync16(uint32_t dst, const void* src) {
    asm volatile("cp.async.cg.shared.global [%0], [%1], 16;" :: "r"(dst), "l"(src));
}
__device__ __forceinline__ void ldsm4(uint32_t* r, uint32_t a) {
    asm volatile("ldmatrix.sync.aligned.m8n8.x4.shared.b16 {%0,%1,%2,%3}, [%4];"
                 : "=r"(r[0]), "=r"(r[1]), "=r"(r[2]), "=r"(r[3]) : "r"(a));
}
__device__ __forceinline__ void mma16816(float* d, const uint32_t* a, const uint32_t* b) {
    asm volatile("mma.sync.aligned.m16n8k16.row.col.f32.bf16.bf16.f32 "
                 "{%0,%1,%2,%3}, {%4,%5,%6,%7}, {%8,%9}, {%0,%1,%2,%3};"
                 : "+f"(d[0]), "+f"(d[1]), "+f"(d[2]), "+f"(d[3])
                 : "r"(a[0]), "r"(a[1]), "r"(a[2]), "r"(a[3]), "r"(b[0]), "r"(b[1]));
}
__device__ __forceinline__ float sigf(float x) {
    return __fdividef(1.0f, 1.0f + __expf(-x));
}
__device__ __forceinline__ float tanhf_fast(float x) {
    float e = __expf(2.0f * x);
    return 1.0f - __fdividef(2.0f, e + 1.0f);
}

// -------------------- smem geometry ----------------------------------------
#define A_SZ        4096               // 64 rows x 32 k bf16 (64B rows)
#define B_SZ        8192               // 128 rows x 32 k bf16
#define B_OFF       16384              // after 4 A tiles
#define STAGE_BYTES 114688             // 112KB
#define SMEM_TOTAL  (2 * STAGE_BYTES)  // 224KB
// epilogue staging: 4 planes x 64 x 132 fp32 = 132KB (reuses stage smem)
#define STG_PITCH   132
#define STG_PLANE   (64 * STG_PITCH)

// ---------------------------------------------------------------------------
// kPre: conversions + M. Blocks 0..8191 split X/H/Wih/Whh; last block does
// g_M = w_read @ W_write.
// ---------------------------------------------------------------------------
__global__ void kPre(const float* __restrict__ X, const float* __restrict__ H,
                     const float* __restrict__ Wih, const float* __restrict__ Whh,
                     const float* __restrict__ wread, const float* __restrict__ wwrite) {
    if (blockIdx.x == gridDim.x - 1) {
        for (int o = threadIdx.x; o < KDIM * KDIM; o += blockDim.x) {
            int hp = o >> 7, h = o & 127;
            float s = 0.0f;
            #pragma unroll 8
            for (int k = 0; k < 64; ++k)
                s = fmaf(wread[hp * 64 + k], wwrite[k * 128 + h], s);
            g_M[o] = s;
        }
        return;
    }
    int i = blockIdx.x * blockDim.x + threadIdx.x;
    if (i < NA) {
        float v = X[i];
        __nv_bfloat16 h = __float2bfloat16(v);
        g_Asp[i] = h;
        g_Asp[NA + i] = __float2bfloat16(v - __bfloat162float(h));
        v = H[i];
        h = __float2bfloat16(v);
        g_Asp[2 * NA + i] = h;
        g_Asp[3 * NA + i] = __float2bfloat16(v - __bfloat162float(h));
    }
    if (i < NW) {
        int rule = i / 49152;
        int rem  = i - rule * 49152;
        int row384 = rem >> 7, k = rem & 127;
        int g = row384 >> 7, rowg = row384 & 127;
        size_t dst = ((size_t)rule * 128 + rowg) * 128 + k;
        const size_t AS = (size_t)RULES * 128 * 128;     // per-arr slab elems
        float v = Wih[i];
        __nv_bfloat16 h = __float2bfloat16(v);
        g_Wsp[(size_t)(g * 2) * AS + dst] = h;
        g_Wsp[(size_t)(g * 2 + 1) * AS + dst] = __float2bfloat16(v - __bfloat162float(h));
        v = Whh[i];
        h = __float2bfloat16(v);
        g_Wsp[(size_t)((3 + g) * 2) * AS + dst] = h;
        g_Wsp[(size_t)((3 + g) * 2 + 1) * AS + dst] = __float2bfloat16(v - __bfloat162float(h));
    }
}

// ---------------------------------------------------------------------------
// kQ: g_q = H @ g_M (fp32; feeds argmax path)
// ---------------------------------------------------------------------------
__global__ void kQ(const float* __restrict__ Hin) {
    __shared__ float Hs[16][KDIM];
    int b0 = blockIdx.x * 16;
    for (int i = threadIdx.x; i < 16 * KDIM; i += blockDim.x)
        Hs[i >> 7][i & 127] = Hin[b0 * KDIM + i];
    __syncthreads();

    int h  = threadIdx.x & 127;
    int rr = threadIdx.x >> 7;
    float acc[8];
    #pragma unroll
    for (int j = 0; j < 8; ++j) acc[j] = 0.0f;
    for (int k = 0; k < KDIM; ++k) {
        float m = g_M[k * KDIM + h];
        #pragma unroll
        for (int j = 0; j < 8; ++j)
            acc[j] = fmaf(Hs[rr + 2 * j][k], m, acc[j]);
    }
    #pragma unroll
    for (int j = 0; j < 8; ++j)
        g_q[(size_t)(b0 + rr + 2 * j) * KDIM + h] = acc[j];
}

// ---------------------------------------------------------------------------
// kGRU stage loader: 1024 threads, 7 x cp.async(16B) each.
// ---------------------------------------------------------------------------
__device__ __forceinline__ void load_stage(uint32_t stb, int b0, int rule,
                                           int tid, int k0) {
    // A: 4 tiles x 64 rows x 4 chunks = 1024 ops (1/thread)
    {
        int tile = tid >> 8;
        int row  = (tid >> 2) & 63;
        int cc   = tid & 3;
        uint32_t sw = (uint32_t)((cc ^ ((row >> 1) & 3)) << 4);
        const __nv_bfloat16* src =
            g_Asp + (size_t)tile * NA + (size_t)(b0 + row) * KDIM + k0 + cc * 8;
        cpasync16(stb + tile * A_SZ + row * 64 + sw, src);
    }
    // B: 12 arrs x 128 rows x 4 chunks = 6144 ops (6/thread)
    #pragma unroll
    for (int a = 0; a < 6; ++a) {
        int idx = a * 1024 + tid;
        int arr = idx >> 9;
        int row = (idx >> 2) & 127;
        int cc  = idx & 3;
        uint32_t sw = (uint32_t)((cc ^ ((row >> 1) & 3)) << 4);
        const __nv_bfloat16* src =
            g_Wsp + ((size_t)arr * RULES + rule) * (128 * KDIM) + (size_t)row * KDIM + k0 + cc * 8;
        cpasync16(stb + B_OFF + arr * B_SZ + row * 64 + sw, src);
    }
    asm volatile("cp.async.commit_group;" ::: "memory");
}

// ---------------------------------------------------------------------------
// kGRU: grid (256, 16), block 1024 = 32 warps.
// Warp w: rg = w&3 (16-row group), u = w>>2: gh = u>>2 (heavy: 0=r,1=z),
// n-quarter = (u&3)*32. Light plane (i_n for gh=0 / h_n for gh=1) done when
// s == gh. Accums: accH[4 nt][4], accL[4 nt][4] = 32 fp32/thread.
// ---------------------------------------------------------------------------
__global__ void __launch_bounds__(1024, 1)
kGRU(const float* __restrict__ Hin,
     const float* __restrict__ bih, const float* __restrict__ bhh) {
    extern __shared__ char smem[];
    const uint32_t sb = smem_u32(smem);
    const int tid = threadIdx.x;
    const int w = tid >> 5, lane = tid & 31;
    const int b0 = blockIdx.x * TM;
    const int rule = blockIdx.y;

    const int rg = w & 3;
    const int u  = w >> 2;
    const int gh = u >> 2;
    const int n0 = (u & 3) * 32;

    // A ldsm4 addressing: matrices (m0k0, m8k0, m0k8, m8k8)
    const int rowa = rg * 16 + ((lane >> 3) & 1) * 8 + (lane & 7);
    const uint32_t aoff = (uint32_t)rowa * 64;
    const int swa = (rowa >> 1) & 3;
    const int hiA = lane >> 4;
    // B ldsm4 addressing: matrices (n0k0, n0k8, n8k0, n8k8) -> regs b0,b1 of
    // nt_even then nt_odd
    const int nbase = n0 + ((lane >> 4) & 1) * 8 + (lane & 7);
    const uint32_t boff0 = (uint32_t)nbase * 64;
    const uint32_t boff1 = (uint32_t)(nbase + 16) * 64;
    const int swb0 = (nbase >> 1) & 3;
    const int swb1 = ((nbase + 16) >> 1) & 3;
    const int hiB = (lane >> 3) & 1;

    float accH[4][4], accL[4][4];
    #pragma unroll
    for (int nt = 0; nt < 4; ++nt)
        #pragma unroll
        for (int j = 0; j < 4; ++j) { accH[nt][j] = 0.0f; accL[nt][j] = 0.0f; }

    load_stage(sb, b0, rule, tid, 0);
    load_stage(sb + STAGE_BYTES, b0, rule, tid, 32);

    for (int c = 0; c < 4; ++c) {
        if (c < 3) asm volatile("cp.async.wait_group 1;" ::: "memory");
        else       asm volatile("cp.async.wait_group 0;" ::: "memory");
        __syncthreads();

        const uint32_t stb = sb + (c & 1) * STAGE_BYTES;
        #pragma unroll
        for (int ks = 0; ks < 2; ++ks) {
            const uint32_t kxa  = (uint32_t)(((ks * 2 + hiA) ^ swa) << 4);
            const uint32_t kxb0 = (uint32_t)(((ks * 2 + hiB) ^ swb0) << 4);
            const uint32_t kxb1 = (uint32_t)(((ks * 2 + hiB) ^ swb1) << 4);
            #pragma unroll
            for (int s = 0; s < 2; ++s) {
                uint32_t ah[4], al[4];
                const uint32_t abase = stb + (uint32_t)(s * 2) * A_SZ + aoff;
                ldsm4(ah, abase + kxa);
                ldsm4(al, abase + A_SZ + kxa);

                const uint32_t hb = stb + B_OFF + (uint32_t)((s * 3 + gh) * 2) * B_SZ;
                {
                    uint32_t bh[4], bl[4];
                    ldsm4(bh, hb + boff0 + kxb0);
                    ldsm4(bl, hb + B_SZ + boff0 + kxb0);
                    mma16816(accH[0], ah, bh + 0); mma16816(accH[0], ah, bl + 0);
                    mma16816(accH[0], al, bh + 0);
                    mma16816(accH[1], ah, bh + 2); mma16816(accH[1], ah, bl + 2);
                    mma16816(accH[1], al, bh + 2);
                }
                {
                    uint32_t bh[4], bl[4];
                    ldsm4(bh, hb + boff1 + kxb1);
                    ldsm4(bl, hb + B_SZ + boff1 + kxb1);
                    mma16816(accH[2], ah, bh + 0); mma16816(accH[2], ah, bl + 0);
                    mma16816(accH[2], al, bh + 0);
                    mma16816(accH[3], ah, bh + 2); mma16816(accH[3], ah, bl + 2);
                    mma16816(accH[3], al, bh + 2);
                }
                if (s == gh) {   // light plane: i_n (s=0) / h_n (s=1)
                    const uint32_t lb = stb + B_OFF + (uint32_t)((s * 3 + 2) * 2) * B_SZ;
                    {
                        uint32_t bh[4], bl[4];
                        ldsm4(bh, lb + boff0 + kxb0);
                        ldsm4(bl, lb + B_SZ + boff0 + kxb0);
                        mma16816(accL[0], ah, bh + 0); mma16816(accL[0], ah, bl + 0);
                        mma16816(accL[0], al, bh + 0);
                        mma16816(accL[1], ah, bh + 2); mma16816(accL[1], ah, bl + 2);
                        mma16816(accL[1], al, bh + 2);
                    }
                    {
                        uint32_t bh[4], bl[4];
                        ldsm4(bh, lb + boff1 + kxb1);
                        ldsm4(bl, lb + B_SZ + boff1 + kxb1);
                        mma16816(accL[2], ah, bh + 0); mma16816(accL[2], ah, bl + 0);
                        mma16816(accL[2], al, bh + 0);
                        mma16816(accL[3], ah, bh + 2); mma16816(accL[3], ah, bl + 2);
                        mma16816(accL[3], al, bh + 2);
                    }
                }
            }
        }
        if (c < 2) {
            __syncthreads();
            load_stage(sb + (c & 1) * STAGE_BYTES, b0, rule, tid, (c + 2) * 32);
        }
    }
    __syncthreads();

    // ---- stage accums: planes r,z,i_n,h_n at pitch 132 (bank-shift)
    float* stg = (float*)smem;
    {
        const int prow  = rg * 16 + (lane >> 2);
        const int pcolb = n0 + (lane & 3) * 2;
        #pragma unroll
        for (int nt = 0; nt < 4; ++nt) {
            float* pH = stg + gh * STG_PLANE + prow * STG_PITCH + pcolb + nt * 8;
            pH[0] = accH[nt][0]; pH[1] = accH[nt][1];
            pH[8 * STG_PITCH] = accH[nt][2]; pH[8 * STG_PITCH + 1] = accH[nt][3];
            float* pL = stg + (2 + gh) * STG_PLANE + prow * STG_PITCH + pcolb + nt * 8;
            pL[0] = accL[nt][0]; pL[1] = accL[nt][1];
            pL[8 * STG_PITCH] = accL[nt][2]; pL[8 * STG_PITCH + 1] = accL[nt][3];
        }
    }
    __syncthreads();

    // ---- gates + logits + store: thread -> (row, 8 cols)
    {
        const int row = tid >> 4;
        const int c0  = (tid & 15) * 8;
        const size_t bg = (size_t)(b0 + row);
        const float* bi = bih + rule * 384;
        const float* bh = bhh + rule * 384;
        const float* hprow = Hin + bg * KDIM;
        const float* qrow  = g_q + bg * KDIM;
        float out[8];
        float dot = 0.0f;
        #pragma unroll
        for (int q = 0; q < 8; ++q) {
            int cc = c0 + q;
            float ar  = stg[                row * STG_PITCH + cc] + bi[cc] + bh[cc];
            float az  = stg[STG_PLANE +     row * STG_PITCH + cc] + bi[128 + cc] + bh[128 + cc];
            float xin = stg[2 * STG_PLANE + row * STG_PITCH + cc] + bi[256 + cc];
            float xhn = stg[3 * STG_PLANE + row * STG_PITCH + cc] + bh[256 + cc];
            float rgate = sigf(ar);
            float zgate = sigf(az);
            float nn = tanhf_fast(fmaf(rgate, xhn, xin));
            out[q] = fmaf(zgate, hprow[cc] - nn, nn);
            dot = fmaf(qrow[cc], out[q], dot);
        }
        #pragma unroll
        for (int off = 8; off; off >>= 1)
            dot += __shfl_xor_sync(0xffffffffu, dot, off);
        if ((tid & 15) == 0)
            g_logits[bg * RULES + rule] = dot;

        float* dst = g_hnext + (bg * RULES + rule) * KDIM + c0;
        *reinterpret_cast<float4*>(dst)     = *reinterpret_cast<const float4*>(&out[0]);
        *reinterpret_cast<float4*>(dst + 4) = *reinterpret_cast<const float4*>(&out[4]);
    }
}

// ---------------------------------------------------------------------------
// kSelect: gather-only. One warp per b: argmax(logits+gumbel), copy winning
// row, one-hot attn.
// ---------------------------------------------------------------------------
__global__ void kSelect(const float* __restrict__ gumbel,
                        float* __restrict__ out_h, float* __restrict__ out_attn) {
    int gwarp = (blockIdx.x * blockDim.x + threadIdx.x) >> 5;
    int lane = threadIdx.x & 31;
    if (gwarp >= BTOT) return;
    const int b = gwarp;

    float bv = -__int_as_float(0x7f800000);
    if (lane < RULES)
        bv = g_logits[b * RULES + lane] + gumbel[b * RULES + lane];
    int bi = lane;
    #pragma unroll
    for (int off = 16; off; off >>= 1) {
        float ov = __shfl_xor_sync(0xffffffffu, bv, off);
        int   oi = __shfl_xor_sync(0xffffffffu, bi, off);
        if (ov > bv || (ov == bv && oi < bi)) { bv = ov; bi = oi; }
    }
    int rbest = bi;

    float4 hv = *reinterpret_cast<const float4*>(
        g_hnext + ((size_t)b * RULES + rbest) * KDIM + lane * 4);
    *reinterpret_cast<float4*>(out_h + (size_t)b * KDIM + lane * 4) = hv;
    if (out_attn && lane < RULES)
        out_attn[b * RULES + lane] = (lane == rbest) ? 1.0f : 0.0f;
}

// ---------------------------------------------------------------------------
extern "C" void kernel_launch(void* const* d_in, const int* in_sizes, int n_in,
                              void* d_out, int out_size) {
    const float* X      = (const float*)d_in[0];
    const float* H      = (const float*)d_in[1];
    const float* Wih    = (const float*)d_in[2];
    const float* Whh    = (const float*)d_in[3];
    const float* bih    = (const float*)d_in[4];
    const float* bhh    = (const float*)d_in[5];
    const float* wread  = (const float*)d_in[6];
    const float* wwrite = (const float*)d_in[7];
    const float* gum    = (const float*)d_in[8];
    float* out = (float*)d_out;

    cudaFuncSetAttribute(kGRU, cudaFuncAttributeMaxDynamicSharedMemorySize, SMEM_TOTAL);

    kPre<<<NA / 256 + 1, 256>>>(X, H, Wih, Whh, wread, wwrite);
    kQ<<<BTOT / 16, 256>>>(H);

    dim3 grid(BTOT / TM, RULES);
    kGRU<<<grid, 1024, SMEM_TOTAL>>>(H, bih, bhh);

    const int HO = BTOT * KDIM;
    float* attn = (out_size >= HO + BTOT * RULES) ? out + HO : nullptr;
    kSelect<<<BTOT / 8, 256>>>(gum, out, attn);
}